// round 13
// baseline (speedup 1.0000x reference)
#include <cuda_runtime.h>
#include <cstdint>

// Problem constants
#define BATCH 32
#define SEQ_T 2048
#define HENC 1024
#define DH 1024              // 2*HD, offset of We within W

#define CHUNKS 32
#define CHUNK_ROWS (SEQ_T / CHUNKS)   // 64
#define TILE_R 4
#define NTHREADS 256
#define TILE_BYTES (TILE_R * HENC * 4)   // 16384
#define TOTAL_CHUNKS (BATCH * CHUNKS)    // 1024

// Persistent grid: exactly the resident set (148 SMs x 5 CTAs)
#define NSM 148
#define CTAS_PER_SM 5
#define GRID (NSM * CTAS_PER_SM)         // 740

// Scratch (allocation-free rule: __device__ globals)
__device__ float g_ctx[TOTAL_CHUNKS * HENC];
__device__ float g_l[TOTAL_CHUNKS];
__device__ int   g_cnt[BATCH];   // per-batch ticket
__device__ int   g_work;         // work queue head (zero-init, reset at end)
__device__ int   g_done;         // finisher count  (zero-init, reset at end)

__device__ __forceinline__ uint32_t smem_u32(const void* p) {
    return (uint32_t)__cvta_generic_to_shared(p);
}
__device__ __forceinline__ void mbar_init(uint32_t mbar, uint32_t cnt) {
    asm volatile("mbarrier.init.shared.b64 [%0], %1;" :: "r"(mbar), "r"(cnt) : "memory");
}
__device__ __forceinline__ void mbar_expect_tx(uint32_t mbar, uint32_t bytes) {
    asm volatile("mbarrier.arrive.expect_tx.shared.b64 _, [%0], %1;"
                 :: "r"(mbar), "r"(bytes) : "memory");
}
__device__ __forceinline__ void bulk_g2s(uint32_t sdst, const void* gsrc,
                                         uint32_t bytes, uint32_t mbar) {
    asm volatile("cp.async.bulk.shared::cta.global.mbarrier::complete_tx::bytes"
                 " [%0], [%1], %2, [%3];"
                 :: "r"(sdst), "l"(gsrc), "r"(bytes), "r"(mbar) : "memory");
}
__device__ __forceinline__ void mbar_wait(uint32_t mbar, uint32_t parity) {
    uint32_t done;
    do {
        asm volatile(
            "{\n\t.reg .pred p;\n\t"
            "mbarrier.try_wait.parity.acquire.cta.shared::cta.b64 p, [%1], %2, 0x989680;\n\t"
            "selp.b32 %0, 1, 0, p;\n\t}"
            : "=r"(done) : "r"(mbar), "r"(parity) : "memory");
    } while (!done);
}

__global__ __launch_bounds__(NTHREADS, CTAS_PER_SM)
void attn_fused_kernel(const float* __restrict__ enc,
                       const float* __restrict__ mask,
                       const float* __restrict__ W,
                       float* __restrict__ out)
{
    __shared__ alignas(128) float s_tile[2][TILE_R][HENC];   // 32 KB
    __shared__ alignas(16)  float s_we[HENC];                // 4 KB
    __shared__ alignas(8) unsigned long long s_mbar[2];
    __shared__ float s_wgt[TILE_R];
    __shared__ float c_inv;
    __shared__ int   s_work;
    __shared__ int   s_last;

    const int tid  = threadIdx.x;
    const int w    = tid >> 5;
    const int lane = tid & 31;

    if (tid == 0) { mbar_init(smem_u32(&s_mbar[0]), 1);
                    mbar_init(smem_u32(&s_mbar[1]), 1); }
    ((float4*)s_we)[tid] = ((const float4*)(W + DH))[tid];   // stage We once
    __syncthreads();

    // mbarrier phase bits persist across chunks (uniform across the CTA)
    uint32_t ph0 = 0, ph1 = 0;

    for (;;) {
        // ---- pull next chunk from the global queue ----
        if (tid == 0) s_work = atomicAdd(&g_work, 1);
        __syncthreads();
        const int job = s_work;
        __syncthreads();          // s_work consumed before next overwrite
        if (job >= TOTAL_CHUNKS) break;

        const int b = job / CHUNKS;
        const int c = job % CHUNKS;
        const float* __restrict__ maskb = mask + b * SEQ_T;
        const int row0 = c * CHUNK_ROWS;

        const int nlive = __syncthreads_count(
            (tid < CHUNK_ROWS) && (maskb[row0 + tid] != 0.0f));

        float4 ctx = make_float4(0.f, 0.f, 0.f, 0.f);
        float  l   = 0.0f;   // only thread 0's copy is used

        if (nlive > 0) {
            const char* __restrict__ encb =
                (const char*)(enc + ((size_t)b * SEQ_T + row0) * HENC);
            const int ntiles = (nlive + TILE_R - 1) / TILE_R;

            if (tid == 0) {
                uint32_t m0 = smem_u32(&s_mbar[0]);
                mbar_expect_tx(m0, TILE_BYTES);
                bulk_g2s(smem_u32(&s_tile[0][0][0]), encb, TILE_BYTES, m0);
                if (ntiles > 1) {
                    uint32_t m1 = smem_u32(&s_mbar[1]);
                    mbar_expect_tx(m1, TILE_BYTES);
                    bulk_g2s(smem_u32(&s_tile[1][0][0]), encb + TILE_BYTES,
                             TILE_BYTES, m1);
                }
            }

            for (int t = 0; t < ntiles; t++) {
                const int buf = t & 1;
                if (buf == 0) { mbar_wait(smem_u32(&s_mbar[0]), ph0); ph0 ^= 1; }
                else          { mbar_wait(smem_u32(&s_mbar[1]), ph1); ph1 ^= 1; }

                // Energies: warp r dots row r with We. No max shift needed:
                // energies are O(1); hid@Wh shift + mask renorm cancel.
                if (w < TILE_R) {
                    const float4* rowp = (const float4*)&s_tile[buf][w][0];
                    const float4* wep  = (const float4*)s_we;
                    float dot = 0.0f;
                    #pragma unroll
                    for (int k = 0; k < 8; k++) {
                        float4 v  = rowp[lane + 32 * k];
                        float4 wv = wep [lane + 32 * k];
                        dot += v.x * wv.x + v.y * wv.y + v.z * wv.z + v.w * wv.w;
                    }
                    #pragma unroll
                    for (int s = 16; s > 0; s >>= 1)
                        dot += __shfl_xor_sync(0xffffffffu, dot, s);
                    if (lane == 0)
                        s_wgt[w] = (t * TILE_R + w < nlive) ? __expf(dot) : 0.0f;
                }
                __syncthreads();   // weights visible

                {
                    const float w0 = s_wgt[0], w1 = s_wgt[1];
                    const float w2 = s_wgt[2], w3 = s_wgt[3];
                    float4 v0 = ((const float4*)&s_tile[buf][0][0])[tid];
                    float4 v1 = ((const float4*)&s_tile[buf][1][0])[tid];
                    float4 v2 = ((const float4*)&s_tile[buf][2][0])[tid];
                    float4 v3 = ((const float4*)&s_tile[buf][3][0])[tid];
                    ctx.x += w0*v0.x + w1*v1.x + w2*v2.x + w3*v3.x;
                    ctx.y += w0*v0.y + w1*v1.y + w2*v2.y + w3*v3.y;
                    ctx.z += w0*v0.z + w1*v1.z + w2*v2.z + w3*v3.z;
                    ctx.w += w0*v0.w + w1*v1.w + w2*v2.w + w3*v3.w;
                    if (tid == 0) l += w0 + w1 + w2 + w3;
                }
                __syncthreads();   // buffer consumed -> safe to refill

                if (t + 2 < ntiles && tid == 0) {
                    uint32_t mb = smem_u32(&s_mbar[buf]);
                    mbar_expect_tx(mb, TILE_BYTES);
                    bulk_g2s(smem_u32(&s_tile[buf][0][0]),
                             encb + (size_t)(t + 2) * TILE_BYTES,
                             TILE_BYTES, mb);
                }
            }
        }

        // Partial for this chunk (zeros if dead — combine reads every slot)
        ((float4*)(g_ctx + (size_t)job * HENC))[tid] = ctx;
        if (tid == 0) g_l[job] = l;

        // ---- per-batch ticket: 32nd chunk of batch b combines it ----
        __threadfence();
        __syncthreads();
        if (tid == 0) {
            int old = atomicAdd(&g_cnt[b], 1);
            s_last = (old == CHUNKS - 1);
            if (s_last) g_cnt[b] = 0;   // restore for graph replay
        }
        __syncthreads();
        if (s_last) {
            __threadfence();   // acquire other chunks' partials
            if (tid == 0) {
                float L = 0.0f;
                #pragma unroll
                for (int c2 = 0; c2 < CHUNKS; c2++) L += g_l[b * CHUNKS + c2];
                c_inv = 1.0f / L;
            }
            __syncthreads();
            float4 acc = make_float4(0.f, 0.f, 0.f, 0.f);
            #pragma unroll
            for (int c2 = 0; c2 < CHUNKS; c2++) {
                float4 v = ((const float4*)(g_ctx +
                              (size_t)(b * CHUNKS + c2) * HENC))[tid];
                acc.x += v.x; acc.y += v.y; acc.z += v.z; acc.w += v.w;
            }
            const float inv = c_inv;
            acc.x *= inv; acc.y *= inv; acc.z *= inv; acc.w *= inv;
            ((float4*)(out + (size_t)b * HENC))[tid] = acc;
            __syncthreads();   // c_inv/s_last safe for next chunk iteration
        }
    }

    // ---- reset queue for next graph replay (last finisher) ----
    if (tid == 0) {
        __threadfence();
        int old = atomicAdd(&g_done, 1);
        if (old == GRID - 1) { g_work = 0; g_done = 0; __threadfence(); }
    }
}

extern "C" void kernel_launch(void* const* d_in, const int* in_sizes, int n_in,
                              void* d_out, int out_size)
{
    // metadata order: hidden, encoder_outputs, mask, W, b
    const float* enc  = (const float*)d_in[1];
    const float* mask = (const float*)d_in[2];
    const float* W    = (const float*)d_in[3];
    float* out        = (float*)d_out;

    attn_fused_kernel<<<GRID, NTHREADS>>>(enc, mask, W, out);
}

// round 14
// speedup vs baseline: 1.1119x; 1.1119x over previous
#include <cuda_runtime.h>
#include <cstdint>

// Problem constants
#define BATCH 32
#define SEQ_T 2048
#define HENC 1024
#define DH 1024              // 2*HD, offset of We within W

#define CHUNKS 32
#define CHUNK_ROWS (SEQ_T / CHUNKS)   // 64
#define TILE_R 4
#define NTHREADS 256
#define TILE_BYTES (TILE_R * HENC * 4)   // 16384
#define TOTAL_CHUNKS (BATCH * CHUNKS)    // 1024

// Scratch (allocation-free rule: __device__ globals)
__device__ float g_ctx[TOTAL_CHUNKS * HENC];
__device__ float g_l[TOTAL_CHUNKS];
__device__ int   g_cnt[BATCH];          // per-batch ticket (self-resetting)
__device__ int   g_joblist[TOTAL_CHUNKS];

__device__ __forceinline__ uint32_t smem_u32(const void* p) {
    return (uint32_t)__cvta_generic_to_shared(p);
}
__device__ __forceinline__ void mbar_init(uint32_t mbar, uint32_t cnt) {
    asm volatile("mbarrier.init.shared.b64 [%0], %1;" :: "r"(mbar), "r"(cnt) : "memory");
}
__device__ __forceinline__ void mbar_expect_tx(uint32_t mbar, uint32_t bytes) {
    asm volatile("mbarrier.arrive.expect_tx.shared.b64 _, [%0], %1;"
                 :: "r"(mbar), "r"(bytes) : "memory");
}
__device__ __forceinline__ void bulk_g2s(uint32_t sdst, const void* gsrc,
                                         uint32_t bytes, uint32_t mbar) {
    asm volatile("cp.async.bulk.shared::cta.global.mbarrier::complete_tx::bytes"
                 " [%0], [%1], %2, [%3];"
                 :: "r"(sdst), "l"(gsrc), "r"(bytes), "r"(mbar) : "memory");
}
__device__ __forceinline__ void mbar_wait(uint32_t mbar, uint32_t parity) {
    uint32_t done;
    do {
        asm volatile(
            "{\n\t.reg .pred p;\n\t"
            "mbarrier.try_wait.parity.acquire.cta.shared::cta.b64 p, [%1], %2, 0x989680;\n\t"
            "selp.b32 %0, 1, 0, p;\n\t}"
            : "=r"(done) : "r"(mbar), "r"(parity) : "memory");
    } while (!done);
}

// ---- Scheduler: compact LIVE chunks to the front of g_joblist ----------
// 1 CTA, 1024 threads. Deterministic (ballot + prefix scan, no atomics).
__global__ __launch_bounds__(1024)
void attn_sched_kernel(const float* __restrict__ mask)
{
    __shared__ int s_wsum[32];    // per-warp live counts
    __shared__ int s_woff[32];    // exclusive scan of warp counts
    __shared__ int s_total;

    const int j    = threadIdx.x;          // job id 0..1023
    const int wid  = j >> 5;
    const int lane = j & 31;

    const int b = j / CHUNKS;
    const int c = j % CHUNKS;
    // Prefix mask: chunk live iff its first row is unmasked.
    const int live = (mask[b * SEQ_T + c * CHUNK_ROWS] != 0.0f) ? 1 : 0;

    const unsigned bal = __ballot_sync(0xffffffffu, live);
    const int lpre = __popc(bal & ((1u << lane) - 1u));   // live before me in warp
    if (lane == 31) s_wsum[wid] = lpre + live;
    __syncthreads();

    if (wid == 0) {
        int v = s_wsum[lane];
        int s = v;
        #pragma unroll
        for (int d = 1; d < 32; d <<= 1) {
            int t = __shfl_up_sync(0xffffffffu, s, d);
            if (lane >= d) s += t;
        }
        s_woff[lane] = s - v;                 // exclusive
        if (lane == 31) s_total = s;          // total live
    }
    __syncthreads();

    const int live_rank = s_woff[wid] + lpre;         // among live
    const int dead_rank = j - live_rank;              // among dead
    const int pos = live ? live_rank : (s_total + dead_rank);
    g_joblist[pos] = j;
}

// ---- Main kernel: R11 TMA pipeline, job = g_joblist[blockIdx.x] --------
__global__ __launch_bounds__(NTHREADS)
void attn_fused_kernel(const float* __restrict__ enc,
                       const float* __restrict__ mask,
                       const float* __restrict__ W,
                       float* __restrict__ out)
{
    __shared__ alignas(128) float s_tile[2][TILE_R][HENC];   // 32 KB
    __shared__ alignas(16)  float s_we[HENC];                // 4 KB
    __shared__ alignas(8) unsigned long long s_mbar[2];
    __shared__ float s_wgt[TILE_R];
    __shared__ float c_inv;
    __shared__ int   s_last;

    const int tid  = threadIdx.x;
    const int job  = g_joblist[blockIdx.x];
    const int b    = job / CHUNKS;
    const int c    = job % CHUNKS;
    const int w    = tid >> 5;
    const int lane = tid & 31;

    const float* __restrict__ maskb = mask + b * SEQ_T;
    const int row0 = c * CHUNK_ROWS;

    if (tid == 0) { mbar_init(smem_u32(&s_mbar[0]), 1);
                    mbar_init(smem_u32(&s_mbar[1]), 1); }
    // Live rows in chunk (prefix mask); doubles as post-init barrier.
    const int nlive = __syncthreads_count(
        (tid < CHUNK_ROWS) && (maskb[row0 + tid] != 0.0f));

    float4 ctx = make_float4(0.f, 0.f, 0.f, 0.f);
    float  l   = 0.0f;   // only thread 0's copy is used

    if (nlive > 0) {
        ((float4*)s_we)[tid] = ((const float4*)(W + DH))[tid];   // stage We

        const char* __restrict__ encb =
            (const char*)(enc + ((size_t)b * SEQ_T + row0) * HENC);
        const int ntiles = (nlive + TILE_R - 1) / TILE_R;

        if (tid == 0) {
            uint32_t m0 = smem_u32(&s_mbar[0]);
            mbar_expect_tx(m0, TILE_BYTES);
            bulk_g2s(smem_u32(&s_tile[0][0][0]), encb, TILE_BYTES, m0);
            if (ntiles > 1) {
                uint32_t m1 = smem_u32(&s_mbar[1]);
                mbar_expect_tx(m1, TILE_BYTES);
                bulk_g2s(smem_u32(&s_tile[1][0][0]), encb + TILE_BYTES,
                         TILE_BYTES, m1);
            }
        }

        for (int t = 0; t < ntiles; t++) {
            const int buf = t & 1;
            mbar_wait(smem_u32(&s_mbar[buf]), (uint32_t)((t >> 1) & 1));

            // Energies: warp r dots row r with We. No max shift needed:
            // energies are O(1); hid@Wh shift + mask renorm cancel.
            if (w < TILE_R) {
                const float4* rowp = (const float4*)&s_tile[buf][w][0];
                const float4* wep  = (const float4*)s_we;
                float dot = 0.0f;
                #pragma unroll
                for (int k = 0; k < 8; k++) {
                    float4 v  = rowp[lane + 32 * k];
                    float4 wv = wep [lane + 32 * k];
                    dot += v.x * wv.x + v.y * wv.y + v.z * wv.z + v.w * wv.w;
                }
                #pragma unroll
                for (int s = 16; s > 0; s >>= 1)
                    dot += __shfl_xor_sync(0xffffffffu, dot, s);
                if (lane == 0)
                    s_wgt[w] = (t * TILE_R + w < nlive) ? __expf(dot) : 0.0f;
            }
            __syncthreads();   // weights visible

            // Channel-parallel accumulate: thread owns channels 4tid..4tid+3
            {
                const float w0 = s_wgt[0], w1 = s_wgt[1];
                const float w2 = s_wgt[2], w3 = s_wgt[3];
                float4 v0 = ((const float4*)&s_tile[buf][0][0])[tid];
                float4 v1 = ((const float4*)&s_tile[buf][1][0])[tid];
                float4 v2 = ((const float4*)&s_tile[buf][2][0])[tid];
                float4 v3 = ((const float4*)&s_tile[buf][3][0])[tid];
                ctx.x += w0*v0.x + w1*v1.x + w2*v2.x + w3*v3.x;
                ctx.y += w0*v0.y + w1*v1.y + w2*v2.y + w3*v3.y;
                ctx.z += w0*v0.z + w1*v1.z + w2*v2.z + w3*v3.z;
                ctx.w += w0*v0.w + w1*v1.w + w2*v2.w + w3*v3.w;
                if (tid == 0) l += w0 + w1 + w2 + w3;
            }
            __syncthreads();   // buffer consumed -> safe to refill

            if (t + 2 < ntiles && tid == 0) {
                uint32_t mb = smem_u32(&s_mbar[buf]);
                mbar_expect_tx(mb, TILE_BYTES);
                bulk_g2s(smem_u32(&s_tile[buf][0][0]),
                         encb + (size_t)(t + 2) * TILE_BYTES, TILE_BYTES, mb);
            }
        }
    }

    // Partial for this chunk (zeros if dead — combine reads every slot)
    ((float4*)(g_ctx + (size_t)job * HENC))[tid] = ctx;
    if (tid == 0) g_l[job] = l;

    // ---- last-CTA-of-batch ticket: combine batch b ----
    __threadfence();
    __syncthreads();
    if (tid == 0) {
        int old = atomicAdd(&g_cnt[b], 1);
        s_last = (old == CHUNKS - 1);
        if (s_last) g_cnt[b] = 0;   // restore invariant for graph replay
    }
    __syncthreads();
    if (!s_last) return;
    __threadfence();   // acquire: other chunks' partials visible

    if (tid == 0) {
        float L = 0.0f;
        #pragma unroll
        for (int c2 = 0; c2 < CHUNKS; c2++) L += g_l[b * CHUNKS + c2];
        c_inv = 1.0f / L;
    }
    __syncthreads();

    {
        float4 acc = make_float4(0.f, 0.f, 0.f, 0.f);
        #pragma unroll
        for (int c2 = 0; c2 < CHUNKS; c2++) {
            float4 v = ((const float4*)(g_ctx +
                          (size_t)(b * CHUNKS + c2) * HENC))[tid];
            acc.x += v.x; acc.y += v.y; acc.z += v.z; acc.w += v.w;
        }
        const float inv = c_inv;
        acc.x *= inv; acc.y *= inv; acc.z *= inv; acc.w *= inv;
        ((float4*)(out + (size_t)b * HENC))[tid] = acc;
    }
}

extern "C" void kernel_launch(void* const* d_in, const int* in_sizes, int n_in,
                              void* d_out, int out_size)
{
    // metadata order: hidden, encoder_outputs, mask, W, b
    const float* enc  = (const float*)d_in[1];
    const float* mask = (const float*)d_in[2];
    const float* W    = (const float*)d_in[3];
    float* out        = (float*)d_out;

    attn_sched_kernel<<<1, 1024>>>(mask);               // live-first joblist
    attn_fused_kernel<<<TOTAL_CHUNKS, NTHREADS>>>(enc, mask, W, out);
}